// round 3
// baseline (speedup 1.0000x reference)
#include <cuda_runtime.h>
#include <cuda_fp16.h>
#include <stdint.h>

#define Bb 256
#define Tt 512
#define Dd 128
#define Hh 512
#define Cc 10

#define NCTA 128
#define NTH  256

// ---- shared memory layout (bytes) ----
#define LDW 520                 // padded row stride in halves (512+8): conflict-free ldmatrix
#define OFF_WF 0                // 32 x 520 halves = 33280 B
#define OFF_WI 33280
#define OFF_WO 66560
#define OFF_A  99840            // c tile, 32 x 520 halves
#define OFF_GATE 133120         // float [32][100]  (f:0-31 | i:32-63 | o:64-95)
#define LDG_ 100
#define OFF_CM 145920           // float [32][33]  master c (fp32)
#define LDCM 33
#define OFF_LUT 150144          // float [4][3][32]
#define SMEM_TOTAL 151680

// ---- device globals (no allocation allowed) ----
__device__ __half g_ch[2][Bb*Hh];        // double-buffered fp16 c exchange
__device__ __half g_Wh[3][Hh*Hh];        // fp16 Wfh, Wih, Woh
__device__ float  g_h[Bb*Hh];            // final hidden state
__device__ float  g_lut[4*3*Hh];         // gate LUT; gate 3 (cs) pre-sigmoided
__device__ unsigned char g_xT[Tt*Bb];    // tokens transposed to [T][B]
__device__ volatile int g_flags[NCTA];   // barrier flags (monotonic step counter)

// =============== setup kernel ===============
__global__ void setup_kernel(const int* __restrict__ x, const float* __restrict__ emb,
    const float* __restrict__ Wfx, const float* __restrict__ bf,
    const float* __restrict__ Wix, const float* __restrict__ bi,
    const float* __restrict__ Wox, const float* __restrict__ bo,
    const float* __restrict__ Wcx, const float* __restrict__ bc,
    const float* __restrict__ Wfh, const float* __restrict__ Wih,
    const float* __restrict__ Woh)
{
    int id = blockIdx.x*blockDim.x + threadIdx.x;
    int n  = gridDim.x*blockDim.x;
    // gate LUT: [gate][val][h]
    for (int i = id; i < 4*3*Hh; i += n){
        int g = i/(3*Hh); int rem = i%(3*Hh); int v = rem/Hh; int h = rem%Hh;
        const float *W, *bb_;
        if      (g==0){ W=Wfx; bb_=bf; }
        else if (g==1){ W=Wix; bb_=bi; }
        else if (g==2){ W=Wox; bb_=bo; }
        else          { W=Wcx; bb_=bc; }
        float s = bb_[h];
        const float* e = emb + v*Dd;
        const float* w = W + (size_t)h*Dd;
        #pragma unroll 4
        for (int d = 0; d < Dd; d++) s += e[d]*w[d];
        if (g==3) s = 1.f/(1.f+expf(-s));   // pre-apply sigmoid to c~ gate
        g_lut[i] = s;
    }
    // zero both c exchange buffers (c0 = 0)
    for (int i = id; i < Bb*Hh; i += n){
        g_ch[0][i] = __float2half(0.f);
        g_ch[1][i] = __float2half(0.f);
    }
    // fp16 recurrent weights
    for (int i = id; i < Hh*Hh; i += n){
        g_Wh[0][i] = __float2half(Wfh[i]);
        g_Wh[1][i] = __float2half(Wih[i]);
        g_Wh[2][i] = __float2half(Woh[i]);
    }
    // transpose tokens
    for (int i = id; i < Tt*Bb; i += n){
        int tt = i / Bb, bb2 = i % Bb;
        g_xT[i] = (unsigned char)x[bb2*Tt + tt];
    }
    for (int i = id; i < NCTA; i += n) g_flags[i] = 0;
}

// =============== PTX helpers ===============
__device__ __forceinline__ void cpa16(uint32_t s, const void* g){
    asm volatile("cp.async.cg.shared.global [%0], [%1], 16;\n" :: "r"(s), "l"(g));
}
__device__ __forceinline__ void cpa_commit_wait(){
    asm volatile("cp.async.commit_group;\n");
    asm volatile("cp.async.wait_group 0;\n");
}
__device__ __forceinline__ void ldsm_x4(uint32_t &r0,uint32_t &r1,uint32_t &r2,uint32_t &r3, uint32_t a){
    asm volatile("ldmatrix.sync.aligned.m8n8.x4.shared.b16 {%0,%1,%2,%3}, [%4];\n"
        : "=r"(r0),"=r"(r1),"=r"(r2),"=r"(r3) : "r"(a));
}
__device__ __forceinline__ void ldsm_x2(uint32_t &r0,uint32_t &r1, uint32_t a){
    asm volatile("ldmatrix.sync.aligned.m8n8.x2.shared.b16 {%0,%1}, [%2];\n"
        : "=r"(r0),"=r"(r1) : "r"(a));
}
__device__ __forceinline__ void mma16816(float* c,
    uint32_t a0,uint32_t a1,uint32_t a2,uint32_t a3, uint32_t b0,uint32_t b1){
    asm volatile("mma.sync.aligned.m16n8k16.row.col.f32.f16.f16.f32 "
        "{%0,%1,%2,%3},{%4,%5,%6,%7},{%8,%9},{%0,%1,%2,%3};\n"
        : "+f"(c[0]),"+f"(c[1]),"+f"(c[2]),"+f"(c[3])
        : "r"(a0),"r"(a1),"r"(a2),"r"(a3),"r"(b0),"r"(b1));
}
__device__ __forceinline__ float sigm(float x){ return 1.f/(1.f+__expf(-x)); }

// =============== persistent LSTM kernel ===============
__global__ void __launch_bounds__(NTH, 1) lstm_kernel()
{
    extern __shared__ char smem[];
    uint32_t sbase = (uint32_t)__cvta_generic_to_shared(smem);
    int tid = threadIdx.x;
    int cta = blockIdx.x;
    int jt = cta & 15;           // h tile
    int mt = cta >> 4;           // batch tile
    int b0 = mt*32, h0 = jt*32;

    float* sGate = (float*)(smem + OFF_GATE);
    float* sCm   = (float*)(smem + OFF_CM);
    float* sLut  = (float*)(smem + OFF_LUT);

    // --- preload weight slices (once) via cp.async ---
    for (int i = tid; i < 3*2048; i += NTH){
        int gsel = i >> 11;           // 2048 16B-chunks per gate
        int r    = (i >> 6) & 31;     // row 0..31
        int ck   = i & 63;            // 16B chunk within row
        uint32_t off = (gsel==0) ? OFF_WF : (gsel==1) ? OFF_WI : OFF_WO;
        uint32_t dst = sbase + off + (uint32_t)(r*LDW + ck*8)*2;
        cpa16(dst, &g_Wh[gsel][(size_t)(h0+r)*Hh + ck*8]);
    }
    // LUT slice + master c init
    for (int i = tid; i < 4*3*32; i += NTH){
        int g = i/96, v = (i/32)%3, h = i%32;
        sLut[i] = g_lut[(g*3+v)*Hh + h0 + h];
    }
    for (int i = tid; i < 32*LDCM; i += NTH) sCm[i] = 0.f;
    cpa_commit_wait();
    __syncthreads();

    // --- per-warp mma geometry ---
    int wid = tid >> 5, lane = tid & 31;
    int mb = wid >> 2, nb = wid & 3;
    int m0 = mb*16;
    int g4 = lane >> 2, t4 = lane & 3;
    // A fragment addresses (16x16 tile): row = m0 + (lane&15), col = ((lane>>4)&1)*8 + k0
    uint32_t aA0 = sbase + OFF_A +
        (uint32_t)(((m0 + (lane & 15))*LDW) + ((lane >> 4) & 1)*8)*2;
    // B fragment addresses for f|i (two n8 blocks per warp)
    uint32_t offW = (nb < 2) ? OFF_WF : OFF_WI;
    int rowB = (nb & 1)*16 + (lane & 7) + ((lane & 16) ? 8 : 0);
    uint32_t aB0 = sbase + offW + (uint32_t)(rowB*LDW + ((lane >> 3) & 1)*8)*2;
    // B for o-gate (last step): warp covers one n8 block
    int rowBo = nb*8 + (lane & 7);
    uint32_t aBo0 = sbase + OFF_WO + (uint32_t)(rowBo*LDW + ((lane >> 3) & 1)*8)*2;

    for (int t = 0; t < Tt; t++){
        int buf = t & 1;
        // --- load c tile (32 x 512 fp16), L1-bypassing ---
        const __half* csrc = g_ch[buf] + (size_t)b0*Hh;
        #pragma unroll
        for (int i = tid; i < 2048; i += NTH){
            int r = i >> 6, ck = i & 63;
            uint32_t dst = sbase + OFF_A + (uint32_t)(r*LDW + ck*8)*2;
            cpa16(dst, csrc + r*Hh + ck*8);
        }
        cpa_commit_wait();
        __syncthreads();

        // --- GEMM: [32b x 512k] x [64n x 512k]^T  (f | i) ---
        float acc0[4] = {0,0,0,0}, acc1[4] = {0,0,0,0};
        #pragma unroll 8
        for (int ks = 0; ks < 32; ks++){
            uint32_t a0,a1,a2,a3,w0,w1,w2,w3;
            ldsm_x4(a0,a1,a2,a3, aA0 + ks*32);
            ldsm_x4(w0,w1,w2,w3, aB0 + ks*32);
            mma16816(acc0, a0,a1,a2,a3, w0,w1);
            mma16816(acc1, a0,a1,a2,a3, w2,w3);
        }
        int r0w = m0 + g4;
        int cb  = nb*16 + t4*2;
        sGate[r0w*LDG_ + cb]       = acc0[0];
        sGate[r0w*LDG_ + cb+1]     = acc0[1];
        sGate[(r0w+8)*LDG_ + cb]   = acc0[2];
        sGate[(r0w+8)*LDG_ + cb+1] = acc0[3];
        sGate[r0w*LDG_ + cb+8]     = acc1[0];
        sGate[r0w*LDG_ + cb+9]     = acc1[1];
        sGate[(r0w+8)*LDG_ + cb+8] = acc1[2];
        sGate[(r0w+8)*LDG_ + cb+9] = acc1[3];

        if (t == Tt-1){
            // o-gate matvec (only needed once)
            float acco[4] = {0,0,0,0};
            #pragma unroll 8
            for (int ks = 0; ks < 32; ks++){
                uint32_t a0,a1,a2,a3,w0,w1;
                ldsm_x4(a0,a1,a2,a3, aA0 + ks*32);
                ldsm_x2(w0,w1, aBo0 + ks*32);
                mma16816(acco, a0,a1,a2,a3, w0,w1);
            }
            int co = 64 + nb*8 + t4*2;
            sGate[r0w*LDG_ + co]       = acco[0];
            sGate[r0w*LDG_ + co+1]     = acco[1];
            sGate[(r0w+8)*LDG_ + co]   = acco[2];
            sGate[(r0w+8)*LDG_ + co+1] = acco[3];
        }
        __syncthreads();

        // --- elementwise cell update (fp32 master state in SMEM) ---
        const unsigned char* xrow = g_xT + t*Bb + b0;
        #pragma unroll
        for (int e = 0; e < 4; e++){
            int ent = e*NTH + tid;
            int bb = ent >> 5, hh = ent & 31;
            int v = (int)xrow[bb];
            float gf = sGate[bb*LDG_ + hh]      + sLut[(0*3+v)*32 + hh];
            float gi = sGate[bb*LDG_ + 32 + hh] + sLut[(1*3+v)*32 + hh];
            float f  = sigm(gf);
            float ii = sigm(gi);
            float cm = sCm[bb*LDCM + hh];
            float cn = sLut[(3*3+v)*32 + hh]*ii + cm*f;
            sCm[bb*LDCM + hh] = cn;
            if (t < Tt-1){
                g_ch[buf^1][(size_t)(b0+bb)*Hh + h0 + hh] = __float2half(cn);
            } else {
                float go = sGate[bb*LDG_ + 64 + hh] + sLut[(2*3+v)*32 + hh];
                g_h[(size_t)(b0+bb)*Hh + h0 + hh] = tanhf(cn) * sigm(go);
            }
        }

        // --- grid barrier (monotonic flags, 1 per step) ---
        if (t < Tt-1){
            __syncthreads();
            if (tid == 0){
                __threadfence();
                g_flags[cta] = t+1;
            }
            if (tid < NCTA){
                while (g_flags[tid] < t+1) { }
                __threadfence();
            }
            __syncthreads();
        }
    }
}

// =============== classifier + log_softmax ===============
__global__ void cls_kernel(const float* __restrict__ Wph, const float* __restrict__ bp,
                           float* __restrict__ out)
{
    int b = blockIdx.x, lane = threadIdx.x;
    const float* hr = g_h + (size_t)b*Hh;
    float p[Cc];
    #pragma unroll
    for (int c = 0; c < Cc; c++){
        float s = 0.f;
        for (int k = lane; k < Hh; k += 32) s += hr[k]*Wph[c*Hh + k];
        #pragma unroll
        for (int o = 16; o; o >>= 1) s += __shfl_xor_sync(0xffffffffu, s, o);
        p[c] = s + bp[c];
    }
    float mx = p[0];
    #pragma unroll
    for (int c = 1; c < Cc; c++) mx = fmaxf(mx, p[c]);
    float se = 0.f;
    #pragma unroll
    for (int c = 0; c < Cc; c++) se += expf(p[c]-mx);
    float lse = mx + logf(se);
    if (lane < Cc) out[b*Cc + lane] = p[lane] - lse;
}

// =============== launch ===============
extern "C" void kernel_launch(void* const* d_in, const int* in_sizes, int n_in,
                              void* d_out, int out_size)
{
    const int*   x   = (const int*)  d_in[0];
    const float* emb = (const float*)d_in[1];
    const float* Wfx = (const float*)d_in[2];
    const float* Wfh = (const float*)d_in[3];
    const float* bf  = (const float*)d_in[4];
    const float* Wix = (const float*)d_in[5];
    const float* Wih = (const float*)d_in[6];
    const float* bi  = (const float*)d_in[7];
    const float* Wox = (const float*)d_in[8];
    const float* Woh = (const float*)d_in[9];
    const float* bo  = (const float*)d_in[10];
    const float* Wcx = (const float*)d_in[11];
    const float* bc  = (const float*)d_in[12];
    const float* Wph = (const float*)d_in[13];
    const float* bp  = (const float*)d_in[14];
    float* out = (float*)d_out;

    cudaFuncSetAttribute(lstm_kernel,
        cudaFuncAttributeMaxDynamicSharedMemorySize, SMEM_TOTAL);

    setup_kernel<<<256,256>>>(x, emb, Wfx, bf, Wix, bi, Wox, bo, Wcx, bc,
                              Wfh, Wih, Woh);
    lstm_kernel<<<NCTA, NTH, SMEM_TOTAL>>>();
    cls_kernel<<<Bb, 32>>>(Wph, bp, out);
}

// round 7
// speedup vs baseline: 1.3347x; 1.3347x over previous
#include <cuda_runtime.h>
#include <cuda_fp16.h>
#include <stdint.h>

#define Bb 256
#define Tt 512
#define Dd 128
#define Hh 512
#define Cc 10

#define NCTA 128
#define NTH  256
#define GRP  16          // CTAs per batch-tile barrier group

// ---- shared memory layout (bytes) ----
#define LDW 520                 // padded row stride in halves (512+8)
#define OFF_WF 0                // 32 x 520 halves = 33280 B
#define OFF_WI 33280
#define OFF_WO 66560
#define OFF_A  99840            // c tile, 32 x 520 halves
#define OFF_GATE 133120         // float [32][100]  (f:0-31 | i:32-63 | o:64-95)
#define LDG_ 100
#define OFF_CM 145920           // float [32][33]  master c (fp32)
#define LDCM 33
#define OFF_LUT 150144          // float [4][3][32]
#define SMEM_TOTAL 151680

// ---- device globals (no allocation allowed) ----
__device__ __half g_ch[2][Bb*Hh];        // double-buffered fp16 c exchange
__device__ __half g_Wh[3][Hh*Hh];        // fp16 Wfh, Wih, Woh
__device__ float  g_h[Bb*Hh];            // final hidden state
__device__ float  g_lut[4*3*Hh];         // gate LUT; gate 3 (cs) pre-sigmoided
__device__ unsigned char g_xT[Tt*Bb];    // tokens transposed to [T][B]
__device__ volatile int g_flags[NCTA];   // per-CTA monotonic step flags

// =============== setup kernel ===============
__global__ void setup_kernel(const int* __restrict__ x, const float* __restrict__ emb,
    const float* __restrict__ Wfx, const float* __restrict__ bf,
    const float* __restrict__ Wix, const float* __restrict__ bi,
    const float* __restrict__ Wox, const float* __restrict__ bo,
    const float* __restrict__ Wcx, const float* __restrict__ bc,
    const float* __restrict__ Wfh, const float* __restrict__ Wih,
    const float* __restrict__ Woh)
{
    int id = blockIdx.x*blockDim.x + threadIdx.x;
    int n  = gridDim.x*blockDim.x;
    // gate LUT: [gate][val][h]
    for (int i = id; i < 4*3*Hh; i += n){
        int g = i/(3*Hh); int rem = i%(3*Hh); int v = rem/Hh; int h = rem%Hh;
        const float *W, *bb_;
        if      (g==0){ W=Wfx; bb_=bf; }
        else if (g==1){ W=Wix; bb_=bi; }
        else if (g==2){ W=Wox; bb_=bo; }
        else          { W=Wcx; bb_=bc; }
        float s = bb_[h];
        const float* e = emb + v*Dd;
        const float* w = W + (size_t)h*Dd;
        #pragma unroll 4
        for (int d = 0; d < Dd; d++) s += e[d]*w[d];
        if (g==3) s = 1.f/(1.f+expf(-s));   // pre-apply sigmoid to c~ gate
        g_lut[i] = s;
    }
    // zero both c exchange buffers (c0 = 0)
    for (int i = id; i < Bb*Hh; i += n){
        g_ch[0][i] = __float2half(0.f);
        g_ch[1][i] = __float2half(0.f);
    }
    // fp16 recurrent weights
    for (int i = id; i < Hh*Hh; i += n){
        g_Wh[0][i] = __float2half(Wfh[i]);
        g_Wh[1][i] = __float2half(Wih[i]);
        g_Wh[2][i] = __float2half(Woh[i]);
    }
    // transpose tokens
    for (int i = id; i < Tt*Bb; i += n){
        int tt = i / Bb, bb2 = i % Bb;
        g_xT[i] = (unsigned char)x[bb2*Tt + tt];
    }
    for (int i = id; i < NCTA; i += n) g_flags[i] = 0;
}

// =============== PTX helpers ===============
__device__ __forceinline__ void cpa16(uint32_t s, const void* g){
    asm volatile("cp.async.cg.shared.global [%0], [%1], 16;\n" :: "r"(s), "l"(g));
}
__device__ __forceinline__ void cpa_commit_wait(){
    asm volatile("cp.async.commit_group;\n");
    asm volatile("cp.async.wait_group 0;\n");
}
__device__ __forceinline__ void ldsm_x4(uint32_t &r0,uint32_t &r1,uint32_t &r2,uint32_t &r3, uint32_t a){
    asm volatile("ldmatrix.sync.aligned.m8n8.x4.shared.b16 {%0,%1,%2,%3}, [%4];\n"
        : "=r"(r0),"=r"(r1),"=r"(r2),"=r"(r3) : "r"(a));
}
__device__ __forceinline__ void ldsm_x2(uint32_t &r0,uint32_t &r1, uint32_t a){
    asm volatile("ldmatrix.sync.aligned.m8n8.x2.shared.b16 {%0,%1}, [%2];\n"
        : "=r"(r0),"=r"(r1) : "r"(a));
}
__device__ __forceinline__ void mma16816(float* c,
    uint32_t a0,uint32_t a1,uint32_t a2,uint32_t a3, uint32_t b0,uint32_t b1){
    asm volatile("mma.sync.aligned.m16n8k16.row.col.f32.f16.f16.f32 "
        "{%0,%1,%2,%3},{%4,%5,%6,%7},{%8,%9},{%0,%1,%2,%3};\n"
        : "+f"(c[0]),"+f"(c[1]),"+f"(c[2]),"+f"(c[3])
        : "r"(a0),"r"(a1),"r"(a2),"r"(a3),"r"(b0),"r"(b1));
}
__device__ __forceinline__ float sigm(float x){ return 1.f/(1.f+__expf(-x)); }

// =============== persistent LSTM kernel ===============
__global__ void __launch_bounds__(NTH, 1) lstm_kernel()
{
    extern __shared__ char smem[];
    uint32_t sbase = (uint32_t)__cvta_generic_to_shared(smem);
    int tid = threadIdx.x;
    int cta = blockIdx.x;
    int jt = cta & 15;           // h tile
    int mt = cta >> 4;           // batch tile (barrier group)
    int b0 = mt*32, h0 = jt*32;

    float* sGate = (float*)(smem + OFF_GATE);
    float* sCm   = (float*)(smem + OFF_CM);
    float* sLut  = (float*)(smem + OFF_LUT);

    // --- preload weight slices (once) via cp.async ---
    for (int i = tid; i < 3*2048; i += NTH){
        int gsel = i >> 11;           // 2048 16B-chunks per gate
        int r    = (i >> 6) & 31;     // row 0..31
        int ck   = i & 63;            // 16B chunk within row
        uint32_t off = (gsel==0) ? OFF_WF : (gsel==1) ? OFF_WI : OFF_WO;
        uint32_t dst = sbase + off + (uint32_t)(r*LDW + ck*8)*2;
        cpa16(dst, &g_Wh[gsel][(size_t)(h0+r)*Hh + ck*8]);
    }
    // LUT slice + master c init
    for (int i = tid; i < 4*3*32; i += NTH){
        int g = i/96, v = (i/32)%3, h = i%32;
        sLut[i] = g_lut[(g*3+v)*Hh + h0 + h];
    }
    for (int i = tid; i < 32*LDCM; i += NTH) sCm[i] = 0.f;
    cpa_commit_wait();
    __syncthreads();

    // --- per-warp mma geometry ---
    int wid = tid >> 5, lane = tid & 31;
    int mb = wid >> 2, nb = wid & 3;
    int m0 = mb*16;
    int g4 = lane >> 2, t4 = lane & 3;
    uint32_t aA0 = sbase + OFF_A +
        (uint32_t)(((m0 + (lane & 15))*LDW) + ((lane >> 4) & 1)*8)*2;
    uint32_t offW = (nb < 2) ? OFF_WF : OFF_WI;
    int rowB = (nb & 1)*16 + (lane & 7) + ((lane & 16) ? 8 : 0);
    uint32_t aB0 = sbase + offW + (uint32_t)(rowB*LDW + ((lane >> 3) & 1)*8)*2;
    int rowBo = nb*8 + (lane & 7);
    uint32_t aBo0 = sbase + OFF_WO + (uint32_t)(rowBo*LDW + ((lane >> 3) & 1)*8)*2;

    for (int t = 0; t < Tt; t++){
        int buf = t & 1;
        // --- load c tile (32 x 512 fp16), monolithic ---
        const __half* csrc = g_ch[buf] + (size_t)b0*Hh;
        #pragma unroll
        for (int i = tid; i < 2048; i += NTH){
            int r = i >> 6, ck = i & 63;
            uint32_t dst = sbase + OFF_A + (uint32_t)(r*LDW + ck*8)*2;
            cpa16(dst, csrc + r*Hh + ck*8);
        }
        cpa_commit_wait();
        __syncthreads();

        // --- GEMM: [32b x 512k] x [64n x 512k]^T  (f | i) ---
        float acc0[4] = {0,0,0,0}, acc1[4] = {0,0,0,0};
        #pragma unroll 8
        for (int ks = 0; ks < 32; ks++){
            uint32_t a0,a1,a2,a3,w0,w1,w2,w3;
            ldsm_x4(a0,a1,a2,a3, aA0 + ks*32);
            ldsm_x4(w0,w1,w2,w3, aB0 + ks*32);
            mma16816(acc0, a0,a1,a2,a3, w0,w1);
            mma16816(acc1, a0,a1,a2,a3, w2,w3);
        }
        int r0w = m0 + g4;
        int cb  = nb*16 + t4*2;
        sGate[r0w*LDG_ + cb]       = acc0[0];
        sGate[r0w*LDG_ + cb+1]     = acc0[1];
        sGate[(r0w+8)*LDG_ + cb]   = acc0[2];
        sGate[(r0w+8)*LDG_ + cb+1] = acc0[3];
        sGate[r0w*LDG_ + cb+8]     = acc1[0];
        sGate[r0w*LDG_ + cb+9]     = acc1[1];
        sGate[(r0w+8)*LDG_ + cb+8] = acc1[2];
        sGate[(r0w+8)*LDG_ + cb+9] = acc1[3];

        if (t == Tt-1){
            // o-gate matvec (only needed once)
            float acco[4] = {0,0,0,0};
            #pragma unroll 8
            for (int ks = 0; ks < 32; ks++){
                uint32_t a0,a1,a2,a3,w0,w1;
                ldsm_x4(a0,a1,a2,a3, aA0 + ks*32);
                ldsm_x2(w0,w1, aBo0 + ks*32);
                mma16816(acco, a0,a1,a2,a3, w0,w1);
            }
            int co = 64 + nb*8 + t4*2;
            sGate[r0w*LDG_ + co]       = acco[0];
            sGate[r0w*LDG_ + co+1]     = acco[1];
            sGate[(r0w+8)*LDG_ + co]   = acco[2];
            sGate[(r0w+8)*LDG_ + co+1] = acco[3];
        }
        __syncthreads();

        // --- elementwise cell update (fp32 master state in SMEM) ---
        const unsigned char* xrow = g_xT + t*Bb + b0;
        #pragma unroll
        for (int e = 0; e < 4; e++){
            int ent = e*NTH + tid;
            int bb = ent >> 5, hh = ent & 31;
            int v = (int)xrow[bb];
            float gf = sGate[bb*LDG_ + hh]      + sLut[(0*3+v)*32 + hh];
            float gi = sGate[bb*LDG_ + 32 + hh] + sLut[(1*3+v)*32 + hh];
            float f  = sigm(gf);
            float ii = sigm(gi);
            float cm = sCm[bb*LDCM + hh];
            float cn = sLut[(3*3+v)*32 + hh]*ii + cm*f;
            sCm[bb*LDCM + hh] = cn;
            if (t < Tt-1){
                g_ch[buf^1][(size_t)(b0+bb)*Hh + h0 + hh] = __float2half(cn);
            } else {
                float go = sGate[bb*LDG_ + 64 + hh] + sLut[(2*3+v)*32 + hh];
                g_h[(size_t)(b0+bb)*Hh + h0 + hh] = tanhf(cn) * sigm(go);
            }
        }

        // --- group-scoped barrier (R2 mechanism, 16-flag poll set) ---
        if (t < Tt-1){
            __syncthreads();
            if (tid == 0){
                __threadfence();
                g_flags[cta] = t+1;
            }
            if (tid < GRP){
                while (g_flags[(mt<<4) + tid] < t+1) { }
                __threadfence();
            }
            __syncthreads();
        }
    }
}

// =============== classifier + log_softmax ===============
__global__ void cls_kernel(const float* __restrict__ Wph, const float* __restrict__ bp,
                           float* __restrict__ out)
{
    int b = blockIdx.x, lane = threadIdx.x;
    const float* hr = g_h + (size_t)b*Hh;
    float p[Cc];
    #pragma unroll
    for (int c = 0; c < Cc; c++){
        float s = 0.f;
        for (int k = lane; k < Hh; k += 32) s += hr[k]*Wph[c*Hh + k];
        #pragma unroll
        for (int o = 16; o; o >>= 1) s += __shfl_xor_sync(0xffffffffu, s, o);
        p[c] = s + bp[c];
    }
    float mx = p[0];
    #pragma unroll
    for (int c = 1; c < Cc; c++) mx = fmaxf(mx, p[c]);
    float se = 0.f;
    #pragma unroll
    for (int c = 0; c < Cc; c++) se += expf(p[c]-mx);
    float lse = mx + logf(se);
    if (lane < Cc) out[b*Cc + lane] = p[lane] - lse;
}

// =============== launch ===============
extern "C" void kernel_launch(void* const* d_in, const int* in_sizes, int n_in,
                              void* d_out, int out_size)
{
    const int*   x   = (const int*)  d_in[0];
    const float* emb = (const float*)d_in[1];
    const float* Wfx = (const float*)d_in[2];
    const float* Wfh = (const float*)d_in[3];
    const float* bf  = (const float*)d_in[4];
    const float* Wix = (const float*)d_in[5];
    const float* Wih = (const float*)d_in[6];
    const float* bi  = (const float*)d_in[7];
    const float* Wox = (const float*)d_in[8];
    const float* Woh = (const float*)d_in[9];
    const float* bo  = (const float*)d_in[10];
    const float* Wcx = (const float*)d_in[11];
    const float* bc  = (const float*)d_in[12];
    const float* Wph = (const float*)d_in[13];
    const float* bp  = (const float*)d_in[14];
    float* out = (float*)d_out;

    cudaFuncSetAttribute(lstm_kernel,
        cudaFuncAttributeMaxDynamicSharedMemorySize, SMEM_TOTAL);

    setup_kernel<<<256,256>>>(x, emb, Wfx, bf, Wix, bi, Wox, bo, Wcx, bc,
                              Wfh, Wih, Woh);
    lstm_kernel<<<NCTA, NTH, SMEM_TOTAL>>>();
    cls_kernel<<<Bb, 32>>>(Wph, bp, out);
}